// round 7
// baseline (speedup 1.0000x reference)
#include <cuda_runtime.h>
#include <cstdint>

#define DIM      512
#define KTOP     5
#define NTHREADS 512
#define NWARPS   (NTHREADS / 32)
#define GROUP    4                    // float4s per thread per iteration (16 elems)
#define PER_ITER (NTHREADS * GROUP)   // float4s per block iteration
#define GRP_MAX  1024                 // hit-group buffer entries
#define CAND_MAX 2048                 // candidate buffer entries
#define SPLIT    2                    // halves per row
#define MAX_PARTS (8192 * SPLIT)      // scratch capacity (parts)

#define NEG_INF (-__int_as_float(0x7F800000))

// Scratch: per-part exact top-5 (value + global index). __device__ globals are
// the allowed scratch mechanism (no allocation in kernel_launch).
__device__ float g_topv[MAX_PARTS * KTOP];
__device__ int   g_topi[MAX_PARTS * KTOP];

// Tie-break identical to jax.lax.top_k: higher value first, then lower index.
__device__ __forceinline__ bool better(float av, int ai, float bv, int bi) {
    return (av > bv) || (av == bv && ai < bi);
}

__device__ __forceinline__ void insert5(float (&v)[KTOP], int (&ix)[KTOP],
                                        float nv, int ni) {
    if (!better(nv, ni, v[KTOP - 1], ix[KTOP - 1])) return;
    v[KTOP - 1] = nv;
    ix[KTOP - 1] = ni;
#pragma unroll
    for (int j = KTOP - 1; j > 0; --j) {
        if (better(v[j], ix[j], v[j - 1], ix[j - 1])) {
            float tv = v[j]; v[j] = v[j - 1]; v[j - 1] = tv;
            int   ti = ix[j]; ix[j] = ix[j - 1]; ix[j - 1] = ti;
        } else {
            break;
        }
    }
}

__device__ __forceinline__ void warp_merge_step(float (&v)[KTOP], int (&ix)[KTOP],
                                                int off) {
    float ov[KTOP];
    int   oi[KTOP];
#pragma unroll
    for (int j = 0; j < KTOP; ++j) {
        ov[j] = __shfl_xor_sync(0xFFFFFFFFu, v[j], off);
        oi[j] = __shfl_xor_sync(0xFFFFFFFFu, ix[j], off);
    }
#pragma unroll
    for (int j = 0; j < KTOP; ++j) insert5(v, ix, ov[j], oi[j]);
}

__device__ __forceinline__ float max4(float4 z) {
    return fmaxf(fmaxf(z.x, z.y), fmaxf(z.z, z.w));
}

// ======================= Kernel A: per-half top-5 scan =======================
__global__ __launch_bounds__(NTHREADS, 4)
void topk_scan_kernel(const float* __restrict__ sp_z, int V, int B) {
    const int bid  = blockIdx.x;           // bid = row * SPLIT + part
    const int row  = bid / SPLIT;
    const int part = bid % SPLIT;
    const int tid  = threadIdx.x;
    const int lane = tid & 31;
    const int warp = tid >> 5;

    __shared__ float s_warpmax[NWARPS];
    __shared__ float s_t;
    __shared__ int   s_gcnt;
    __shared__ int   s_cnt;
    __shared__ int   s_gbase[GRP_MAX];
    __shared__ float s_cand_v[CAND_MAX];
    __shared__ int   s_cand_i[CAND_MAX];

    if (tid == 0) { s_gcnt = 0; s_cnt = 0; }
    __syncthreads();

    const size_t rowbase = (size_t)row * (size_t)V;

    float v[KTOP];
    int   ix[KTOP];
#pragma unroll
    for (int k = 0; k < KTOP; ++k) { v[k] = NEG_INF; ix[k] = 0x7FFFFFFF; }

    if ((V & 3) == 0) {
        const float4* zrow = reinterpret_cast<const float4*>(sp_z + rowbase);
        const int nv4  = V >> 2;
        const int half = (nv4 + SPLIT - 1) / SPLIT;
        const int f0   = part * half;
        const int f1   = min(f0 + half, nv4);
        const int n    = f1 - f0;

        // ---- 1. Threshold: 5th-largest warp-max of first 1024 float4s ----
        // The 5 largest warp-maxes are distinct elements of this half, so
        // t <= this half's 5th-largest element: (z >= t) keeps all top-5
        // AND guarantees >= 5 candidates survive.
        float tmax = NEG_INF;
#pragma unroll
        for (int g = 0; g < 2; ++g) {
            const int i = g * NTHREADS + tid;
            if (i < n) tmax = fmaxf(tmax, max4(__ldg(zrow + f0 + i)));
        }
#pragma unroll
        for (int off = 16; off; off >>= 1)
            tmax = fmaxf(tmax, __shfl_xor_sync(0xFFFFFFFFu, tmax, off));
        if (lane == 0) s_warpmax[warp] = tmax;
        __syncthreads();

        if (warp == 0) {
            float wv = (lane < NWARPS) ? s_warpmax[lane] : NEG_INF;
            float tcur = NEG_INF;
#pragma unroll
            for (int r = 0; r < KTOP; ++r) {
                float m = wv;
#pragma unroll
                for (int off = 16; off; off >>= 1)
                    m = fmaxf(m, __shfl_xor_sync(0xFFFFFFFFu, m, off));
                unsigned msk = __ballot_sync(0xFFFFFFFFu, wv == m);
                int leader = __ffs(msk) - 1;
                if (lane == leader) wv = NEG_INF;
                tcur = m;
            }
            if (lane == 0) s_t = tcur;
        }
        __syncthreads();
        const float t = s_t;

        // ---- 2. Hot loop over this half ----
        const int nfull = n / PER_ITER;
        for (int it = 0; it < nfull; ++it) {
            const int base = f0 + it * PER_ITER + tid;
            float4 z0 = __ldcs(zrow + base);
            float4 z1 = __ldcs(zrow + base +     NTHREADS);
            float4 z2 = __ldcs(zrow + base + 2 * NTHREADS);
            float4 z3 = __ldcs(zrow + base + 3 * NTHREADS);
            const float m = fmaxf(fmaxf(max4(z0), max4(z1)),
                                  fmaxf(max4(z2), max4(z3)));
            if (m >= t) {
                int p = atomicAdd(&s_gcnt, 1);
                if (p < GRP_MAX) s_gbase[p] = base;
            }
        }
        // Tail float4s: push surviving elements directly as candidates.
        for (int i = f0 + nfull * PER_ITER + tid; i < f1; i += NTHREADS) {
            float4 z = __ldcs(zrow + i);
            if (max4(z) >= t) {
                const float zz[4] = {z.x, z.y, z.z, z.w};
#pragma unroll
                for (int r = 0; r < 4; ++r) {
                    if (zz[r] >= t) {
                        int p = atomicAdd(&s_cnt, 1);
                        if (p < CAND_MAX) { s_cand_v[p] = zz[r]; s_cand_i[p] = (i << 2) + r; }
                    }
                }
            }
        }
        __syncthreads();

        // ---- 3. Expand hit groups (16 elems on lanes 0..15) ----
        const int ng = min(s_gcnt, GRP_MAX);
        for (int g = warp; g < ng; g += NWARPS) {
            const int base = s_gbase[g];
            float z = NEG_INF;
            int eidx = 0;
            if (lane < 16) {
                const int q = lane >> 2, r = lane & 3;
                const int fi = base + q * NTHREADS;
                eidx = (fi << 2) + r;
                z = __ldg(sp_z + rowbase + eidx);
            }
            const unsigned msk = __ballot_sync(0xFFFFFFFFu, z >= t);
            const int cnt = __popc(msk);
            int posbase = 0;
            if (lane == 0 && cnt) posbase = atomicAdd(&s_cnt, cnt);
            posbase = __shfl_sync(0xFFFFFFFFu, posbase, 0);
            const int off = __popc(msk & ((1u << lane) - 1));
            if ((z >= t) && (posbase + off) < CAND_MAX) {
                s_cand_v[posbase + off] = z;
                s_cand_i[posbase + off] = eidx;
            }
        }
        __syncthreads();

        // ---- 4. Exact local top-5 over candidates -> global scratch ----
        if (warp == 0) {
            const int nc = min(s_cnt, CAND_MAX);
            for (int c = lane; c < nc; c += 32)
                insert5(v, ix, s_cand_v[c], s_cand_i[c]);
#pragma unroll
            for (int off = 16; off; off >>= 1) warp_merge_step(v, ix, off);
            if (lane == 0) {
#pragma unroll
                for (int k = 0; k < KTOP; ++k) {
                    g_topv[bid * KTOP + k] = v[k];
                    g_topi[bid * KTOP + k] = ix[k];
                }
            }
        }
    } else {
        // Rare fallback: scalar guarded scan of this half.
        const int half = (V + SPLIT - 1) / SPLIT;
        const int e0 = part * half;
        const int e1 = min(e0 + half, V);
        for (int j = e0 + tid; j < e1; j += NTHREADS) {
            float z = __ldg(sp_z + rowbase + j);
            if (z > v[KTOP - 1]) insert5(v, ix, z, j);
        }
#pragma unroll
        for (int off = 16; off; off >>= 1) warp_merge_step(v, ix, off);
        __shared__ float s_wv2[NWARPS][KTOP];
        __shared__ int   s_wi2[NWARPS][KTOP];
        if (lane == 0) {
#pragma unroll
            for (int k = 0; k < KTOP; ++k) { s_wv2[warp][k] = v[k]; s_wi2[warp][k] = ix[k]; }
        }
        __syncthreads();
        if (warp == 0) {
            float mv[KTOP]; int mi[KTOP];
            if (lane < NWARPS) {
#pragma unroll
                for (int k = 0; k < KTOP; ++k) { mv[k] = s_wv2[lane][k]; mi[k] = s_wi2[lane][k]; }
            } else {
#pragma unroll
                for (int k = 0; k < KTOP; ++k) { mv[k] = NEG_INF; mi[k] = 0x7FFFFFFF; }
            }
#pragma unroll
            for (int off = 8; off; off >>= 1) warp_merge_step(mv, mi, off);
            if (lane == 0) {
#pragma unroll
                for (int k = 0; k < KTOP; ++k) {
                    g_topv[bid * KTOP + k] = mv[k];
                    g_topi[bid * KTOP + k] = mi[k];
                }
            }
        }
    }
}

// ================= Kernel B: merge halves + gather + attention =================
__global__ __launch_bounds__(NTHREADS, 4)
void attn_kernel(const float* __restrict__ sp_w,
                 const float* __restrict__ encoded,
                 float* __restrict__ out,
                 float* __restrict__ attn_out,
                 float* __restrict__ idx_out) {
    const int row  = blockIdx.x;
    const int tid  = threadIdx.x;
    const int lane = tid & 31;
    const int warp = tid >> 5;

    __shared__ int   s_idx[KTOP];
    __shared__ float s_red[NWARPS][KTOP];
    __shared__ float s_scores[KTOP];

    // Merge the SPLIT local top-5 lists (exact global tie-break on indices).
    if (warp == 0) {
        float v[KTOP];
        int   ix[KTOP];
        const int ncand = SPLIT * KTOP;   // 10
        if (lane < ncand) {
            v[0]  = g_topv[row * ncand + lane];
            ix[0] = g_topi[row * ncand + lane];
        } else {
            v[0]  = NEG_INF;
            ix[0] = 0x7FFFFFFF;
        }
#pragma unroll
        for (int k = 1; k < KTOP; ++k) { v[k] = NEG_INF; ix[k] = 0x7FFFFFFF; }
#pragma unroll
        for (int off = 16; off; off >>= 1) warp_merge_step(v, ix, off);
        if (lane == 0) {
#pragma unroll
            for (int k = 0; k < KTOP; ++k) s_idx[k] = ix[k];
        }
    }
    __syncthreads();

    const int d = tid;   // DIM == NTHREADS == 512
    const float enc = __ldg(encoded + (size_t)row * DIM + d);

    float w[KTOP];
    float partial[KTOP];
#pragma unroll
    for (int k = 0; k < KTOP; ++k) {
        w[k] = __ldg(sp_w + (size_t)s_idx[k] * DIM + d);
        partial[k] = w[k] * enc;
    }
#pragma unroll
    for (int off = 16; off; off >>= 1) {
#pragma unroll
        for (int k = 0; k < KTOP; ++k)
            partial[k] += __shfl_down_sync(0xFFFFFFFFu, partial[k], off);
    }
    if (lane == 0) {
#pragma unroll
        for (int k = 0; k < KTOP; ++k) s_red[warp][k] = partial[k];
    }
    __syncthreads();
    if (tid < KTOP) {
        float s = 0.f;
#pragma unroll
        for (int wq = 0; wq < NWARPS; ++wq) s += s_red[wq][tid];
        s_scores[tid] = s;
    }
    __syncthreads();

    float sc[KTOP];
#pragma unroll
    for (int k = 0; k < KTOP; ++k) sc[k] = s_scores[k];
    float mx = sc[0];
#pragma unroll
    for (int k = 1; k < KTOP; ++k) mx = fmaxf(mx, sc[k]);
    float e[KTOP];
    float esum = 0.f;
#pragma unroll
    for (int k = 0; k < KTOP; ++k) { e[k] = expf(sc[k] - mx); esum += e[k]; }
    const float inv = 1.0f / esum;

    float acc = 0.f;
#pragma unroll
    for (int k = 0; k < KTOP; ++k) acc += w[k] * (e[k] * inv);
    out[(size_t)row * DIM + d] = acc;

    if (tid < KTOP) {
        if (attn_out) attn_out[(size_t)row * KTOP + tid] = e[tid] * inv;
        if (idx_out)  idx_out[(size_t)row * KTOP + tid] = (float)s_idx[tid];
    }
}

extern "C" void kernel_launch(void* const* d_in, const int* in_sizes, int n_in,
                              void* d_out, int out_size) {
    const float* sp_z    = (const float*)d_in[0];  // [B, V]
    const float* sp_w    = (const float*)d_in[1];  // [V, DIM]
    const float* encoded = (const float*)d_in[2];  // [B, DIM]

    const int B = in_sizes[2] / DIM;
    const int V = in_sizes[0] / B;

    float* out = (float*)d_out;
    float* attn_out = nullptr;
    float* idx_out  = nullptr;
    if (out_size >= B * (DIM + KTOP))     attn_out = out + (size_t)B * DIM;
    if (out_size >= B * (DIM + 2 * KTOP)) idx_out  = out + (size_t)B * (DIM + KTOP);

    topk_scan_kernel<<<B * SPLIT, NTHREADS>>>(sp_z, V, B);
    attn_kernel<<<B, NTHREADS>>>(sp_w, encoded, out, attn_out, idx_out);
}

// round 8
// speedup vs baseline: 1.0879x; 1.0879x over previous
#include <cuda_runtime.h>
#include <cstdint>

#define DIM      512
#define KTOP     5
#define NTHREADS 512
#define NWARPS   (NTHREADS / 32)
#define TILE_F4  512                   // float4s per tile = 8 KB
#define TILE_BYTES (TILE_F4 * 16)
#define NSTAGES  4                     // 32 KB ring
#define GRP_MAX  512
#define CAND_MAX 1024

#define NEG_INF (-__int_as_float(0x7F800000))

// ---------------- mbarrier / bulk-copy PTX helpers ----------------
__device__ __forceinline__ uint32_t smem_u32(const void* p) {
    uint32_t a;
    asm("{ .reg .u64 t; cvta.to.shared.u64 t, %1; cvt.u32.u64 %0, t; }"
        : "=r"(a) : "l"(p));
    return a;
}
#define MBAR_INIT(addr, cnt) \
    asm volatile("mbarrier.init.shared.b64 [%0], %1;" :: "r"(addr), "r"(cnt) : "memory")
#define MBAR_EXPECT_TX(addr, bytes) \
    asm volatile("mbarrier.arrive.expect_tx.shared.b64 _, [%0], %1;" :: "r"(addr), "r"(bytes) : "memory")
#define MBAR_ARRIVE(addr) \
    asm volatile("mbarrier.arrive.shared.b64 _, [%0];" :: "r"(addr) : "memory")
#define MBAR_WAIT(addr, parity) do {                                          \
    uint32_t _m = (addr); uint32_t _p = (parity); uint32_t _done;             \
    asm volatile("{\n\t.reg .pred p;\n\t"                                     \
        "mbarrier.try_wait.parity.acquire.cta.shared::cta.b64 p, [%1], %2;\n\t" \
        "selp.b32 %0, 1, 0, p;\n\t}"                                          \
        : "=r"(_done) : "r"(_m), "r"(_p) : "memory");                         \
    if (!_done) {                                                             \
        asm volatile("{\n\t.reg .pred P1;\n\t"                                \
            "WL_%=:\n\t"                                                      \
            "mbarrier.try_wait.parity.acquire.cta.shared::cta.b64 P1, [%0], %1, 0x989680;\n\t" \
            "@P1 bra.uni WD_%=;\n\t"                                          \
            "bra.uni WL_%=;\n\t"                                              \
            "WD_%=:\n\t}" :: "r"(_m), "r"(_p) : "memory");                    \
    }                                                                         \
} while (0)
#define BULK_G2S(dst_smem, src_gmem, bytes, mbar) \
    asm volatile("cp.async.bulk.shared::cluster.global.mbarrier::complete_tx::bytes " \
                 "[%0], [%1], %2, [%3];"                                      \
                 :: "r"(dst_smem), "l"(src_gmem), "r"(bytes), "r"(mbar) : "memory")

// Tie-break identical to jax.lax.top_k: higher value first, then lower index.
__device__ __forceinline__ bool better(float av, int ai, float bv, int bi) {
    return (av > bv) || (av == bv && ai < bi);
}
__device__ __forceinline__ void insert5(float (&v)[KTOP], int (&ix)[KTOP],
                                        float nv, int ni) {
    if (!better(nv, ni, v[KTOP - 1], ix[KTOP - 1])) return;
    v[KTOP - 1] = nv;
    ix[KTOP - 1] = ni;
#pragma unroll
    for (int j = KTOP - 1; j > 0; --j) {
        if (better(v[j], ix[j], v[j - 1], ix[j - 1])) {
            float tv = v[j]; v[j] = v[j - 1]; v[j - 1] = tv;
            int   ti = ix[j]; ix[j] = ix[j - 1]; ix[j - 1] = ti;
        } else break;
    }
}
__device__ __forceinline__ void warp_merge_step(float (&v)[KTOP], int (&ix)[KTOP],
                                                int off) {
    float ov[KTOP]; int oi[KTOP];
#pragma unroll
    for (int j = 0; j < KTOP; ++j) {
        ov[j] = __shfl_xor_sync(0xFFFFFFFFu, v[j], off);
        oi[j] = __shfl_xor_sync(0xFFFFFFFFu, ix[j], off);
    }
#pragma unroll
    for (int j = 0; j < KTOP; ++j) insert5(v, ix, ov[j], oi[j]);
}
__device__ __forceinline__ float max4(float4 z) {
    return fmaxf(fmaxf(z.x, z.y), fmaxf(z.z, z.w));
}

__global__ __launch_bounds__(NTHREADS, 4)
void fused_topk_attn_kernel(const float* __restrict__ sp_z,
                            const float* __restrict__ sp_w,
                            const float* __restrict__ encoded,
                            float* __restrict__ out,
                            float* __restrict__ attn_out,
                            float* __restrict__ idx_out,
                            int V) {
    const int row  = blockIdx.x;
    const int tid  = threadIdx.x;
    const int lane = tid & 31;
    const int warp = tid >> 5;

    __shared__ __align__(16) float4 s_tile[NSTAGES][TILE_F4];     // 32 KB
    __shared__ __align__(8) unsigned long long s_full[NSTAGES];
    __shared__ __align__(8) unsigned long long s_empty[NSTAGES];
    __shared__ float s_warpmax[NWARPS];
    __shared__ float s_t;
    __shared__ int   s_gcnt, s_cnt;
    __shared__ int   s_gbase[GRP_MAX];
    __shared__ float s_cand_v[CAND_MAX];
    __shared__ int   s_cand_i[CAND_MAX];
    __shared__ int   s_idx[KTOP];
    __shared__ float s_red[NWARPS][KTOP];
    __shared__ float s_scores[KTOP];
    __shared__ float s_wv2[NWARPS][KTOP];
    __shared__ int   s_wi2[NWARPS][KTOP];

    const size_t rowbase = (size_t)row * (size_t)V;

    if ((V & 3) == 0) {
        const float4* zrow = reinterpret_cast<const float4*>(sp_z + rowbase);
        const int nv4    = V >> 2;
        const int ntiles = nv4 / TILE_F4;

        uint32_t mb_full[NSTAGES], mb_empty[NSTAGES];
#pragma unroll
        for (int s = 0; s < NSTAGES; ++s) {
            mb_full[s]  = smem_u32(&s_full[s]);
            mb_empty[s] = smem_u32(&s_empty[s]);
        }

        if (tid == 0) {
            s_gcnt = 0; s_cnt = 0;
#pragma unroll
            for (int s = 0; s < NSTAGES; ++s) {
                MBAR_INIT(mb_full[s], 1);
                MBAR_INIT(mb_empty[s], NTHREADS);
            }
            asm volatile("fence.proxy.async.shared::cta;" ::: "memory");
        }
        __syncthreads();

        // Prologue: issue up to NSTAGES tiles.
        if (tid == 0) {
            const int npro = ntiles < NSTAGES ? ntiles : NSTAGES;
            for (int s = 0; s < npro; ++s) {
                MBAR_EXPECT_TX(mb_full[s], TILE_BYTES);
                BULK_G2S(smem_u32(&s_tile[s][0]),
                         (const void*)(zrow + s * TILE_F4), TILE_BYTES, mb_full[s]);
            }
        }

        // ---- 1. Threshold from tile 0 (in smem): 5th-largest warp-max ----
        // t <= 5th-largest element of tile 0 <= row's 5th element, so the
        // (z >= t) filter provably keeps every top-5 element and leaves >=5.
        float t;
        if (ntiles > 0) {
            MBAR_WAIT(mb_full[0], 0);
            float tmax = max4(s_tile[0][tid]);
#pragma unroll
            for (int off = 16; off; off >>= 1)
                tmax = fmaxf(tmax, __shfl_xor_sync(0xFFFFFFFFu, tmax, off));
            if (lane == 0) s_warpmax[warp] = tmax;
            __syncthreads();
            if (warp == 0) {
                float wv = (lane < NWARPS) ? s_warpmax[lane] : NEG_INF;
                float tcur = NEG_INF;
#pragma unroll
                for (int r = 0; r < KTOP; ++r) {
                    float m = wv;
#pragma unroll
                    for (int off = 16; off; off >>= 1)
                        m = fmaxf(m, __shfl_xor_sync(0xFFFFFFFFu, m, off));
                    unsigned msk = __ballot_sync(0xFFFFFFFFu, wv == m);
                    if (lane == __ffs(msk) - 1) wv = NEG_INF;
                    tcur = m;
                }
                if (lane == 0) s_t = tcur;
            }
            __syncthreads();
            t = s_t;
        } else {
            t = NEG_INF;
        }

        // ---- 2. Pipelined scan: TMA fills ring, threads filter from smem ----
        for (int ti = 0; ti < ntiles; ++ti) {
            const int st = ti & (NSTAGES - 1);
            const int ph = (ti >> 2) & 1;
            MBAR_WAIT(mb_full[st], ph);
            const float4 z = s_tile[st][tid];
            if (max4(z) >= t) {                    // rare: push global f4 index
                int p = atomicAdd(&s_gcnt, 1);
                if (p < GRP_MAX) s_gbase[p] = ti * TILE_F4 + tid;
            }
            MBAR_ARRIVE(mb_empty[st]);
            if (tid == 0 && ti + NSTAGES < ntiles) {
                MBAR_WAIT(mb_empty[st], ph);       // all 512 consumed this round
                MBAR_EXPECT_TX(mb_full[st], TILE_BYTES);
                BULK_G2S(smem_u32(&s_tile[st][0]),
                         (const void*)(zrow + (ti + NSTAGES) * TILE_F4),
                         TILE_BYTES, mb_full[st]);
            }
        }
        // Tail float4s straight from global.
        for (int i = ntiles * TILE_F4 + tid; i < nv4; i += NTHREADS) {
            float4 z = __ldg(zrow + i);
            if (max4(z) >= t) {
                const float zz[4] = {z.x, z.y, z.z, z.w};
#pragma unroll
                for (int r = 0; r < 4; ++r) {
                    if (zz[r] >= t) {
                        int p = atomicAdd(&s_cnt, 1);
                        if (p < CAND_MAX) { s_cand_v[p] = zz[r]; s_cand_i[p] = (i << 2) + r; }
                    }
                }
            }
        }
        __syncthreads();

        // ---- 3. Expand hit groups (4 elems each, 8 groups per warp) ----
        {
            const int ng = min(s_gcnt, GRP_MAX);
            for (int g0 = warp * 8; g0 < ng; g0 += NWARPS * 8) {
                const int gl = g0 + (lane >> 2);
                float z = NEG_INF; int eidx = 0;
                if (gl < ng) {
                    eidx = (s_gbase[gl] << 2) + (lane & 3);
                    z = __ldg(sp_z + rowbase + eidx);
                }
                const unsigned msk = __ballot_sync(0xFFFFFFFFu, z >= t);
                const int cnt = __popc(msk);
                int posbase = 0;
                if (lane == 0 && cnt) posbase = atomicAdd(&s_cnt, cnt);
                posbase = __shfl_sync(0xFFFFFFFFu, posbase, 0);
                const int off = __popc(msk & ((1u << lane) - 1));
                if ((z >= t) && (posbase + off) < CAND_MAX) {
                    s_cand_v[posbase + off] = z;
                    s_cand_i[posbase + off] = eidx;
                }
            }
        }
        __syncthreads();

        // ---- 4. Exact top-5 (lax.top_k tie-break) over surviving candidates ----
        if (warp == 0) {
            float v[KTOP]; int ix[KTOP];
#pragma unroll
            for (int k = 0; k < KTOP; ++k) { v[k] = NEG_INF; ix[k] = 0x7FFFFFFF; }
            const int n = min(s_cnt, CAND_MAX);
            for (int c = lane; c < n; c += 32)
                insert5(v, ix, s_cand_v[c], s_cand_i[c]);
#pragma unroll
            for (int off = 16; off; off >>= 1) warp_merge_step(v, ix, off);
            if (lane == 0) {
#pragma unroll
                for (int k = 0; k < KTOP; ++k) s_idx[k] = ix[k];
            }
        }
        __syncthreads();
    } else {
        // Fallback: scalar guarded scan + exact merges.
        float v[KTOP]; int ix[KTOP];
#pragma unroll
        for (int k = 0; k < KTOP; ++k) { v[k] = NEG_INF; ix[k] = 0x7FFFFFFF; }
        for (int j = tid; j < V; j += NTHREADS) {
            float z = __ldg(sp_z + rowbase + j);
            if (z > v[KTOP - 1]) insert5(v, ix, z, j);
        }
#pragma unroll
        for (int off = 16; off; off >>= 1) warp_merge_step(v, ix, off);
        if (lane == 0) {
#pragma unroll
            for (int k = 0; k < KTOP; ++k) { s_wv2[warp][k] = v[k]; s_wi2[warp][k] = ix[k]; }
        }
        __syncthreads();
        if (warp == 0) {
            float mv[KTOP]; int mi[KTOP];
            if (lane < NWARPS) {
#pragma unroll
                for (int k = 0; k < KTOP; ++k) { mv[k] = s_wv2[lane][k]; mi[k] = s_wi2[lane][k]; }
            } else {
#pragma unroll
                for (int k = 0; k < KTOP; ++k) { mv[k] = NEG_INF; mi[k] = 0x7FFFFFFF; }
            }
#pragma unroll
            for (int off = 8; off; off >>= 1) warp_merge_step(mv, mi, off);
            if (lane == 0) {
#pragma unroll
                for (int k = 0; k < KTOP; ++k) s_idx[k] = mi[k];
            }
        }
        __syncthreads();
    }

    // ---------------- Phase 2: gather + attention (unchanged) ----------------
    const int d = tid;   // DIM == NTHREADS == 512
    const float enc = __ldg(encoded + (size_t)row * DIM + d);

    float w[KTOP], partial[KTOP];
#pragma unroll
    for (int k = 0; k < KTOP; ++k) {
        w[k] = __ldg(sp_w + (size_t)s_idx[k] * DIM + d);
        partial[k] = w[k] * enc;
    }
#pragma unroll
    for (int off = 16; off; off >>= 1) {
#pragma unroll
        for (int k = 0; k < KTOP; ++k)
            partial[k] += __shfl_down_sync(0xFFFFFFFFu, partial[k], off);
    }
    if (lane == 0) {
#pragma unroll
        for (int k = 0; k < KTOP; ++k) s_red[warp][k] = partial[k];
    }
    __syncthreads();
    if (tid < KTOP) {
        float s = 0.f;
#pragma unroll
        for (int wq = 0; wq < NWARPS; ++wq) s += s_red[wq][tid];
        s_scores[tid] = s;
    }
    __syncthreads();

    float sc[KTOP];
#pragma unroll
    for (int k = 0; k < KTOP; ++k) sc[k] = s_scores[k];
    float mx = sc[0];
#pragma unroll
    for (int k = 1; k < KTOP; ++k) mx = fmaxf(mx, sc[k]);
    float e[KTOP], esum = 0.f;
#pragma unroll
    for (int k = 0; k < KTOP; ++k) { e[k] = expf(sc[k] - mx); esum += e[k]; }
    const float inv = 1.0f / esum;

    float acc = 0.f;
#pragma unroll
    for (int k = 0; k < KTOP; ++k) acc += w[k] * (e[k] * inv);
    out[(size_t)row * DIM + d] = acc;

    if (tid < KTOP) {
        if (attn_out) attn_out[(size_t)row * KTOP + tid] = e[tid] * inv;
        if (idx_out)  idx_out[(size_t)row * KTOP + tid] = (float)s_idx[tid];
    }
}

extern "C" void kernel_launch(void* const* d_in, const int* in_sizes, int n_in,
                              void* d_out, int out_size) {
    const float* sp_z    = (const float*)d_in[0];  // [B, V]
    const float* sp_w    = (const float*)d_in[1];  // [V, DIM]
    const float* encoded = (const float*)d_in[2];  // [B, DIM]

    const int B = in_sizes[2] / DIM;
    const int V = in_sizes[0] / B;

    float* out = (float*)d_out;
    float* attn_out = nullptr;
    float* idx_out  = nullptr;
    if (out_size >= B * (DIM + KTOP))     attn_out = out + (size_t)B * DIM;
    if (out_size >= B * (DIM + 2 * KTOP)) idx_out  = out + (size_t)B * (DIM + KTOP);

    fused_topk_attn_kernel<<<B, NTHREADS>>>(sp_z, sp_w, encoded,
                                            out, attn_out, idx_out, V);
}

// round 9
// speedup vs baseline: 1.0905x; 1.0023x over previous
#include <cuda_runtime.h>
#include <cstdint>

#define DIM      512
#define KTOP     5
#define NTHREADS 512
#define NWARPS   (NTHREADS / 32)
#define TILE_F4  512                   // float4s per tile = 8 KB
#define TILE_BYTES (TILE_F4 * 16)
#define NSTAGES  4                     // 32 KB ring
#define GRP_MAX  512
#define CAND_MAX 1024

#define NEG_INF (-__int_as_float(0x7F800000))

// ---------------- mbarrier / bulk-copy PTX helpers ----------------
__device__ __forceinline__ uint32_t smem_u32(const void* p) {
    uint32_t a;
    asm("{ .reg .u64 t; cvta.to.shared.u64 t, %1; cvt.u32.u64 %0, t; }"
        : "=r"(a) : "l"(p));
    return a;
}
#define MBAR_INIT(addr, cnt) \
    asm volatile("mbarrier.init.shared.b64 [%0], %1;" :: "r"(addr), "r"(cnt) : "memory")
#define MBAR_EXPECT_TX(addr, bytes) \
    asm volatile("mbarrier.arrive.expect_tx.shared.b64 _, [%0], %1;" :: "r"(addr), "r"(bytes) : "memory")
#define MBAR_ARRIVE(addr) \
    asm volatile("mbarrier.arrive.shared.b64 _, [%0];" :: "r"(addr) : "memory")
#define MBAR_WAIT(addr, parity) do {                                          \
    uint32_t _m = (addr); uint32_t _p = (parity); uint32_t _done;             \
    asm volatile("{\n\t.reg .pred p;\n\t"                                     \
        "mbarrier.try_wait.parity.acquire.cta.shared::cta.b64 p, [%1], %2;\n\t" \
        "selp.b32 %0, 1, 0, p;\n\t}"                                          \
        : "=r"(_done) : "r"(_m), "r"(_p) : "memory");                         \
    if (!_done) {                                                             \
        asm volatile("{\n\t.reg .pred P1;\n\t"                                \
            "WL_%=:\n\t"                                                      \
            "mbarrier.try_wait.parity.acquire.cta.shared::cta.b64 P1, [%0], %1, 0x989680;\n\t" \
            "@P1 bra.uni WD_%=;\n\t"                                          \
            "bra.uni WL_%=;\n\t"                                              \
            "WD_%=:\n\t}" :: "r"(_m), "r"(_p) : "memory");                    \
    }                                                                         \
} while (0)
#define BULK_G2S(dst_smem, src_gmem, bytes, mbar) \
    asm volatile("cp.async.bulk.shared::cluster.global.mbarrier::complete_tx::bytes " \
                 "[%0], [%1], %2, [%3];"                                      \
                 :: "r"(dst_smem), "l"(src_gmem), "r"(bytes), "r"(mbar) : "memory")

// Tie-break identical to jax.lax.top_k: higher value first, then lower index.
__device__ __forceinline__ bool better(float av, int ai, float bv, int bi) {
    return (av > bv) || (av == bv && ai < bi);
}
__device__ __forceinline__ void insert5(float (&v)[KTOP], int (&ix)[KTOP],
                                        float nv, int ni) {
    if (!better(nv, ni, v[KTOP - 1], ix[KTOP - 1])) return;
    v[KTOP - 1] = nv;
    ix[KTOP - 1] = ni;
#pragma unroll
    for (int j = KTOP - 1; j > 0; --j) {
        if (better(v[j], ix[j], v[j - 1], ix[j - 1])) {
            float tv = v[j]; v[j] = v[j - 1]; v[j - 1] = tv;
            int   ti = ix[j]; ix[j] = ix[j - 1]; ix[j - 1] = ti;
        } else break;
    }
}
__device__ __forceinline__ void warp_merge_step(float (&v)[KTOP], int (&ix)[KTOP],
                                                int off) {
    float ov[KTOP]; int oi[KTOP];
#pragma unroll
    for (int j = 0; j < KTOP; ++j) {
        ov[j] = __shfl_xor_sync(0xFFFFFFFFu, v[j], off);
        oi[j] = __shfl_xor_sync(0xFFFFFFFFu, ix[j], off);
    }
#pragma unroll
    for (int j = 0; j < KTOP; ++j) insert5(v, ix, ov[j], oi[j]);
}
__device__ __forceinline__ float max4(float4 z) {
    return fmaxf(fmaxf(z.x, z.y), fmaxf(z.z, z.w));
}

__global__ __launch_bounds__(NTHREADS, 4)
void fused_topk_attn_kernel(const float* __restrict__ sp_z,
                            const float* __restrict__ sp_w,
                            const float* __restrict__ encoded,
                            float* __restrict__ out,
                            float* __restrict__ attn_out,
                            float* __restrict__ idx_out,
                            int V) {
    const int row  = blockIdx.x;
    const int tid  = threadIdx.x;
    const int lane = tid & 31;
    const int warp = tid >> 5;

    __shared__ __align__(16) float4 s_tile[NSTAGES][TILE_F4];     // 32 KB
    __shared__ __align__(8) unsigned long long s_full[NSTAGES];
    __shared__ __align__(8) unsigned long long s_empty[NSTAGES];
    __shared__ float s_warpmax[NWARPS];
    __shared__ float s_t;
    __shared__ int   s_gcnt, s_cnt;
    __shared__ int   s_gbase[GRP_MAX];
    __shared__ float s_cand_v[CAND_MAX];
    __shared__ int   s_cand_i[CAND_MAX];
    __shared__ int   s_idx[KTOP];
    __shared__ float s_red[NWARPS][KTOP];
    __shared__ float s_scores[KTOP];
    __shared__ float s_wv2[NWARPS][KTOP];
    __shared__ int   s_wi2[NWARPS][KTOP];

    const size_t rowbase = (size_t)row * (size_t)V;

    if ((V & 3) == 0) {
        const float4* zrow = reinterpret_cast<const float4*>(sp_z + rowbase);
        const int nv4    = V >> 2;
        const int ntiles = nv4 / TILE_F4;

        uint32_t mb_full[NSTAGES], mb_empty[NSTAGES];
#pragma unroll
        for (int s = 0; s < NSTAGES; ++s) {
            mb_full[s]  = smem_u32(&s_full[s]);
            mb_empty[s] = smem_u32(&s_empty[s]);
        }

        if (tid == 0) {
            s_gcnt = 0; s_cnt = 0;
#pragma unroll
            for (int s = 0; s < NSTAGES; ++s) {
                MBAR_INIT(mb_full[s], 1);
                MBAR_INIT(mb_empty[s], NWARPS);   // warp-elected arrives (16, not 512)
            }
            asm volatile("fence.proxy.async.shared::cta;" ::: "memory");
        }
        __syncthreads();

        // Prologue: issue up to NSTAGES tiles (32 KB in flight per CTA).
        if (tid == 0) {
            const int npro = ntiles < NSTAGES ? ntiles : NSTAGES;
            for (int s = 0; s < npro; ++s) {
                MBAR_EXPECT_TX(mb_full[s], TILE_BYTES);
                BULK_G2S(smem_u32(&s_tile[s][0]),
                         (const void*)(zrow + s * TILE_F4), TILE_BYTES, mb_full[s]);
            }
        }

        // ---- 1. Threshold from tile 0 (in smem): 5th-largest warp-max ----
        // t <= 5th-largest element of tile 0 <= row's 5th element, so the
        // (z >= t) filter provably keeps every top-5 element and leaves >=5.
        float t;
        if (ntiles > 0) {
            MBAR_WAIT(mb_full[0], 0);
            float tmax = max4(s_tile[0][tid]);
#pragma unroll
            for (int off = 16; off; off >>= 1)
                tmax = fmaxf(tmax, __shfl_xor_sync(0xFFFFFFFFu, tmax, off));
            if (lane == 0) s_warpmax[warp] = tmax;
            __syncthreads();
            if (warp == 0) {
                float wv = (lane < NWARPS) ? s_warpmax[lane] : NEG_INF;
                float tcur = NEG_INF;
#pragma unroll
                for (int r = 0; r < KTOP; ++r) {
                    float m = wv;
#pragma unroll
                    for (int off = 16; off; off >>= 1)
                        m = fmaxf(m, __shfl_xor_sync(0xFFFFFFFFu, m, off));
                    unsigned msk = __ballot_sync(0xFFFFFFFFu, wv == m);
                    if (lane == __ffs(msk) - 1) wv = NEG_INF;
                    tcur = m;
                }
                if (lane == 0) s_t = tcur;
            }
            __syncthreads();
            t = s_t;
        } else {
            t = NEG_INF;
        }

        // ---- 2. Pipelined scan: TMA fills ring, light per-warp arrives ----
        for (int ti = 0; ti < ntiles; ++ti) {
            const int st = ti & (NSTAGES - 1);
            const int ph = (ti >> 2) & 1;
            MBAR_WAIT(mb_full[st], ph);
            const float4 z = s_tile[st][tid];
            if (max4(z) >= t) {                    // rare: push global f4 index
                int p = atomicAdd(&s_gcnt, 1);
                if (p < GRP_MAX) s_gbase[p] = ti * TILE_F4 + tid;
            }
            __syncwarp();                          // all lanes consumed this tile
            if (lane == 0) MBAR_ARRIVE(mb_empty[st]);
            if (tid == 0 && ti + NSTAGES < ntiles) {
                MBAR_WAIT(mb_empty[st], ph);       // 16 warps consumed this round
                MBAR_EXPECT_TX(mb_full[st], TILE_BYTES);
                BULK_G2S(smem_u32(&s_tile[st][0]),
                         (const void*)(zrow + (ti + NSTAGES) * TILE_F4),
                         TILE_BYTES, mb_full[st]);
            }
        }
        // Tail float4s straight from global.
        for (int i = ntiles * TILE_F4 + tid; i < nv4; i += NTHREADS) {
            float4 z = __ldg(zrow + i);
            if (max4(z) >= t) {
                const float zz[4] = {z.x, z.y, z.z, z.w};
#pragma unroll
                for (int r = 0; r < 4; ++r) {
                    if (zz[r] >= t) {
                        int p = atomicAdd(&s_cnt, 1);
                        if (p < CAND_MAX) { s_cand_v[p] = zz[r]; s_cand_i[p] = (i << 2) + r; }
                    }
                }
            }
        }
        __syncthreads();

        // ---- 3. Expand hit groups (4 elems each, 8 groups per warp) ----
        {
            const int ng = min(s_gcnt, GRP_MAX);
            for (int g0 = warp * 8; g0 < ng; g0 += NWARPS * 8) {
                const int gl = g0 + (lane >> 2);
                float z = NEG_INF; int eidx = 0;
                if (gl < ng) {
                    eidx = (s_gbase[gl] << 2) + (lane & 3);
                    z = __ldg(sp_z + rowbase + eidx);
                }
                const unsigned msk = __ballot_sync(0xFFFFFFFFu, z >= t);
                const int cnt = __popc(msk);
                int posbase = 0;
                if (lane == 0 && cnt) posbase = atomicAdd(&s_cnt, cnt);
                posbase = __shfl_sync(0xFFFFFFFFu, posbase, 0);
                const int off = __popc(msk & ((1u << lane) - 1));
                if ((z >= t) && (posbase + off) < CAND_MAX) {
                    s_cand_v[posbase + off] = z;
                    s_cand_i[posbase + off] = eidx;
                }
            }
        }
        __syncthreads();

        // ---- 4. Exact top-5 (lax.top_k tie-break) over surviving candidates ----
        if (warp == 0) {
            float v[KTOP]; int ix[KTOP];
#pragma unroll
            for (int k = 0; k < KTOP; ++k) { v[k] = NEG_INF; ix[k] = 0x7FFFFFFF; }
            const int n = min(s_cnt, CAND_MAX);
            for (int c = lane; c < n; c += 32)
                insert5(v, ix, s_cand_v[c], s_cand_i[c]);
#pragma unroll
            for (int off = 16; off; off >>= 1) warp_merge_step(v, ix, off);
            if (lane == 0) {
#pragma unroll
                for (int k = 0; k < KTOP; ++k) s_idx[k] = ix[k];
            }
        }
        __syncthreads();
    } else {
        // Fallback: scalar guarded scan + exact merges.
        float v[KTOP]; int ix[KTOP];
#pragma unroll
        for (int k = 0; k < KTOP; ++k) { v[k] = NEG_INF; ix[k] = 0x7FFFFFFF; }
        for (int j = tid; j < V; j += NTHREADS) {
            float z = __ldg(sp_z + rowbase + j);
            if (z > v[KTOP - 1]) insert5(v, ix, z, j);
        }
#pragma unroll
        for (int off = 16; off; off >>= 1) warp_merge_step(v, ix, off);
        if (lane == 0) {
#pragma unroll
            for (int k = 0; k < KTOP; ++k) { s_wv2[warp][k] = v[k]; s_wi2[warp][k] = ix[k]; }
        }
        __syncthreads();
        if (warp == 0) {
            float mv[KTOP]; int mi[KTOP];
            if (lane < NWARPS) {
#pragma unroll
                for (int k = 0; k < KTOP; ++k) { mv[k] = s_wv2[lane][k]; mi[k] = s_wi2[lane][k]; }
            } else {
#pragma unroll
                for (int k = 0; k < KTOP; ++k) { mv[k] = NEG_INF; mi[k] = 0x7FFFFFFF; }
            }
#pragma unroll
            for (int off = 8; off; off >>= 1) warp_merge_step(mv, mi, off);
            if (lane == 0) {
#pragma unroll
                for (int k = 0; k < KTOP; ++k) s_idx[k] = mi[k];
            }
        }
        __syncthreads();
    }

    // ---------------- Phase 2: gather + attention (unchanged) ----------------
    const int d = tid;   // DIM == NTHREADS == 512
    const float enc = __ldg(encoded + (size_t)row * DIM + d);

    float w[KTOP], partial[KTOP];
#pragma unroll
    for (int k = 0; k < KTOP; ++k) {
        w[k] = __ldg(sp_w + (size_t)s_idx[k] * DIM + d);
        partial[k] = w[k] * enc;
    }
#pragma unroll
    for (int off = 16; off; off >>= 1) {
#pragma unroll
        for (int k = 0; k < KTOP; ++k)
            partial[k] += __shfl_down_sync(0xFFFFFFFFu, partial[k], off);
    }
    if (lane == 0) {
#pragma unroll
        for (int k = 0; k < KTOP; ++k) s_red[warp][k] = partial[k];
    }
    __syncthreads();
    if (tid < KTOP) {
        float s = 0.f;
#pragma unroll
        for (int wq = 0; wq < NWARPS; ++wq) s += s_red[wq][tid];
        s_scores[tid] = s;
    }
    __syncthreads();

    float sc[KTOP];
#pragma unroll
    for (int k = 0; k < KTOP; ++k) sc[k] = s_scores[k];
    float mx = sc[0];
#pragma unroll
    for (int k = 1; k < KTOP; ++k) mx = fmaxf(mx, sc[k]);
    float e[KTOP], esum = 0.f;
#pragma unroll
    for (int k = 0; k < KTOP; ++k) { e[k] = expf(sc[k] - mx); esum += e[k]; }
    const float inv = 1.0f / esum;

    float acc = 0.f;
#pragma unroll
    for (int k = 0; k < KTOP; ++k) acc += w[k] * (e[k] * inv);
    out[(size_t)row * DIM + d] = acc;

    if (tid < KTOP) {
        if (attn_out) attn_out[(size_t)row * KTOP + tid] = e[tid] * inv;
        if (idx_out)  idx_out[(size_t)row * KTOP + tid] = (float)s_idx[tid];
    }
}

extern "C" void kernel_launch(void* const* d_in, const int* in_sizes, int n_in,
                              void* d_out, int out_size) {
    const float* sp_z    = (const float*)d_in[0];  // [B, V]
    const float* sp_w    = (const float*)d_in[1];  // [V, DIM]
    const float* encoded = (const float*)d_in[2];  // [B, DIM]

    const int B = in_sizes[2] / DIM;
    const int V = in_sizes[0] / B;

    float* out = (float*)d_out;
    float* attn_out = nullptr;
    float* idx_out  = nullptr;
    if (out_size >= B * (DIM + KTOP))     attn_out = out + (size_t)B * DIM;
    if (out_size >= B * (DIM + 2 * KTOP)) idx_out  = out + (size_t)B * (DIM + KTOP);

    fused_topk_attn_kernel<<<B, NTHREADS>>>(sp_z, sp_w, encoded,
                                            out, attn_out, idx_out, V);
}

// round 10
// speedup vs baseline: 1.2408x; 1.1379x over previous
#include <cuda_runtime.h>
#include <cstdint>

#define DIM      512
#define KTOP     5
#define NTHREADS 512
#define NWARPS   (NTHREADS / 32)
#define GROUP    4                    // float4s per thread per iteration (16 elems)
#define PER_ITER (NTHREADS * GROUP)   // float4s per block iteration
#define GRP_MAX  1024                 // hit-group buffer entries
#define CAND_MAX 2048                 // candidate buffer entries

#define NEG_INF (-__int_as_float(0x7F800000))

// Streaming load with evict-first policy + 256B L2 prefetch hint.
__device__ __forceinline__ float4 ldcs_pf256(const float4* p) {
    float4 r;
    asm volatile("ld.global.cs.L2::256B.v4.f32 {%0,%1,%2,%3}, [%4];"
                 : "=f"(r.x), "=f"(r.y), "=f"(r.z), "=f"(r.w)
                 : "l"(p));
    return r;
}

// Tie-break identical to jax.lax.top_k: higher value first, then lower index.
__device__ __forceinline__ bool better(float av, int ai, float bv, int bi) {
    return (av > bv) || (av == bv && ai < bi);
}

// Insert (nv, ni) into a descending-sorted top-5 list (cold path only).
__device__ __forceinline__ void insert5(float (&v)[KTOP], int (&ix)[KTOP],
                                        float nv, int ni) {
    if (!better(nv, ni, v[KTOP - 1], ix[KTOP - 1])) return;
    v[KTOP - 1] = nv;
    ix[KTOP - 1] = ni;
#pragma unroll
    for (int j = KTOP - 1; j > 0; --j) {
        if (better(v[j], ix[j], v[j - 1], ix[j - 1])) {
            float tv = v[j]; v[j] = v[j - 1]; v[j - 1] = tv;
            int   ti = ix[j]; ix[j] = ix[j - 1]; ix[j - 1] = ti;
        } else {
            break;
        }
    }
}

__device__ __forceinline__ void warp_merge_step(float (&v)[KTOP], int (&ix)[KTOP],
                                                int off) {
    float ov[KTOP];
    int   oi[KTOP];
#pragma unroll
    for (int j = 0; j < KTOP; ++j) {
        ov[j] = __shfl_xor_sync(0xFFFFFFFFu, v[j], off);
        oi[j] = __shfl_xor_sync(0xFFFFFFFFu, ix[j], off);
    }
#pragma unroll
    for (int j = 0; j < KTOP; ++j) insert5(v, ix, ov[j], oi[j]);
}

__device__ __forceinline__ float max4(float4 z) {
    return fmaxf(fmaxf(z.x, z.y), fmaxf(z.z, z.w));
}

// Cap regs at 32/thread so 4 CTAs (64 warps) fit per SM.
__global__ __launch_bounds__(NTHREADS, 4)
void fused_topk_attn_kernel(const float* __restrict__ sp_z,
                            const float* __restrict__ sp_w,
                            const float* __restrict__ encoded,
                            float* __restrict__ out,       // [B, DIM]
                            float* __restrict__ attn_out,  // [B, KTOP] or nullptr
                            float* __restrict__ idx_out,   // [B, KTOP] or nullptr
                            int V) {
    const int row  = blockIdx.x;
    const int tid  = threadIdx.x;
    const int lane = tid & 31;
    const int warp = tid >> 5;

    __shared__ float s_warpmax[NWARPS];
    __shared__ float s_t;
    __shared__ int   s_gcnt;
    __shared__ int   s_cnt;
    __shared__ int   s_gbase[GRP_MAX];
    __shared__ float s_cand_v[CAND_MAX];
    __shared__ int   s_cand_i[CAND_MAX];
    __shared__ int   s_idx[KTOP];
    __shared__ float s_red[NWARPS][KTOP];
    __shared__ float s_scores[KTOP];

    if (tid == 0) { s_gcnt = 0; s_cnt = 0; }

    const size_t rowbase = (size_t)row * (size_t)V;
    const float4* zrow   = reinterpret_cast<const float4*>(sp_z + rowbase);
    const int nv4 = V >> 2;            // V % 4 == 0 for this problem (50000)

    // ---- 1. Threshold: 5th-largest warp-max over the first 2048 float4s ----
    // The top-5 warp-maxes are 5 distinct elements, so t <= global 5th:
    // filtering with (z >= t) provably keeps every global top-5 element.
    float tmax = NEG_INF;
#pragma unroll
    for (int g = 0; g < 4; ++g) {
        const int i = g * NTHREADS + tid;
        if (i < nv4) tmax = fmaxf(tmax, max4(__ldg(zrow + i)));
    }
#pragma unroll
    for (int off = 16; off; off >>= 1)
        tmax = fmaxf(tmax, __shfl_xor_sync(0xFFFFFFFFu, tmax, off));
    if (lane == 0) s_warpmax[warp] = tmax;
    __syncthreads();

    if (warp == 0) {
        float wv = (lane < NWARPS) ? s_warpmax[lane] : NEG_INF;
        float tcur = NEG_INF;
#pragma unroll
        for (int r = 0; r < KTOP; ++r) {
            float m = wv;
#pragma unroll
            for (int off = 16; off; off >>= 1)
                m = fmaxf(m, __shfl_xor_sync(0xFFFFFFFFu, m, off));
            unsigned msk = __ballot_sync(0xFFFFFFFFu, wv == m);
            int leader = __ffs(msk) - 1;
            if (lane == leader) wv = NEG_INF;   // remove exactly one holder
            tcur = m;
        }
        if (lane == 0) s_t = tcur;
    }
    __syncthreads();
    const float t = s_t;

    // ---- 2. Hot loop: 4 independent LDG.128 (+L2 prefetch), one rare push ----
    const int nfull = nv4 / PER_ITER;
    for (int it = 0; it < nfull; ++it) {
        const int base = it * PER_ITER + tid;
        float4 z0 = ldcs_pf256(zrow + base);
        float4 z1 = ldcs_pf256(zrow + base +     NTHREADS);
        float4 z2 = ldcs_pf256(zrow + base + 2 * NTHREADS);
        float4 z3 = ldcs_pf256(zrow + base + 3 * NTHREADS);
        const float m = fmaxf(fmaxf(max4(z0), max4(z1)),
                              fmaxf(max4(z2), max4(z3)));
        if (m >= t) {                        // rare; body is 3 instrs, no sorting
            int p = atomicAdd(&s_gcnt, 1);
            if (p < GRP_MAX) s_gbase[p] = base;
        }
    }
    // Tail float4s: push surviving elements directly as candidates.
    for (int i = nfull * PER_ITER + tid; i < nv4; i += NTHREADS) {
        float4 z = __ldcs(zrow + i);
        if (max4(z) >= t) {
            const float zz[4] = {z.x, z.y, z.z, z.w};
#pragma unroll
            for (int r = 0; r < 4; ++r) {
                if (zz[r] >= t) {
                    int p = atomicAdd(&s_cnt, 1);
                    if (p < CAND_MAX) { s_cand_v[p] = zz[r]; s_cand_i[p] = (i << 2) + r; }
                }
            }
        }
    }

    // Prefetch the context-encoding element now: its latency overlaps the
    // expansion + merge phases below instead of serializing into phase 2.
    const float enc = __ldg(encoded + (size_t)row * DIM + tid);

    __syncthreads();

    // ---- 3. Expand hit groups (16 elems on lanes 0..15): ballot-compact ----
    {
        const int ng = min(s_gcnt, GRP_MAX);
        for (int g = warp; g < ng; g += NWARPS) {
            const int base = s_gbase[g];
            float z = NEG_INF;
            int eidx = 0;
            if (lane < 16) {
                const int q = lane >> 2, r = lane & 3;
                const int fi = base + q * NTHREADS;      // float4 index
                eidx = (fi << 2) + r;
                z = __ldg(sp_z + rowbase + eidx);
            }
            const unsigned msk = __ballot_sync(0xFFFFFFFFu, z >= t);
            const int cnt = __popc(msk);
            int posbase = 0;
            if (lane == 0 && cnt) posbase = atomicAdd(&s_cnt, cnt);
            posbase = __shfl_sync(0xFFFFFFFFu, posbase, 0);
            const int off = __popc(msk & ((1u << lane) - 1));
            if ((z >= t) && (posbase + off) < CAND_MAX) {
                s_cand_v[posbase + off] = z;
                s_cand_i[posbase + off] = eidx;
            }
        }
    }
    __syncthreads();

    // ---- 4. Exact top-5 (with lax.top_k tie-break) over ~30 candidates ----
    if (warp == 0) {
        float v[KTOP];
        int   ix[KTOP];
#pragma unroll
        for (int k = 0; k < KTOP; ++k) { v[k] = NEG_INF; ix[k] = 0x7FFFFFFF; }
        const int n = min(s_cnt, CAND_MAX);
        for (int c = lane; c < n; c += 32)
            insert5(v, ix, s_cand_v[c], s_cand_i[c]);
#pragma unroll
        for (int off = 16; off; off >>= 1) warp_merge_step(v, ix, off);
        if (lane == 0) {
#pragma unroll
            for (int k = 0; k < KTOP; ++k) s_idx[k] = ix[k];
        }
    }
    __syncthreads();

    // ---------------- Phase 2: gather + attention ----------------
    const int d = tid;   // DIM == NTHREADS == 512

    float w[KTOP];
    float partial[KTOP];
#pragma unroll
    for (int k = 0; k < KTOP; ++k) {
        w[k] = __ldg(sp_w + (size_t)s_idx[k] * DIM + d);
        partial[k] = w[k] * enc;
    }
#pragma unroll
    for (int off = 16; off; off >>= 1) {
#pragma unroll
        for (int k = 0; k < KTOP; ++k)
            partial[k] += __shfl_down_sync(0xFFFFFFFFu, partial[k], off);
    }
    if (lane == 0) {
#pragma unroll
        for (int k = 0; k < KTOP; ++k) s_red[warp][k] = partial[k];
    }
    __syncthreads();
    if (tid < KTOP) {
        float s = 0.f;
#pragma unroll
        for (int wq = 0; wq < NWARPS; ++wq) s += s_red[wq][tid];
        s_scores[tid] = s;
    }
    __syncthreads();

    float sc[KTOP];
#pragma unroll
    for (int k = 0; k < KTOP; ++k) sc[k] = s_scores[k];
    float mx = sc[0];
#pragma unroll
    for (int k = 1; k < KTOP; ++k) mx = fmaxf(mx, sc[k]);
    float e[KTOP];
    float esum = 0.f;
#pragma unroll
    for (int k = 0; k < KTOP; ++k) { e[k] = expf(sc[k] - mx); esum += e[k]; }
    const float inv = 1.0f / esum;

    float acc = 0.f;
#pragma unroll
    for (int k = 0; k < KTOP; ++k) acc += w[k] * (e[k] * inv);
    out[(size_t)row * DIM + d] = acc;

    if (tid < KTOP) {
        if (attn_out) attn_out[(size_t)row * KTOP + tid] = e[tid] * inv;
        if (idx_out)  idx_out[(size_t)row * KTOP + tid] = (float)s_idx[tid];
    }
}

extern "C" void kernel_launch(void* const* d_in, const int* in_sizes, int n_in,
                              void* d_out, int out_size) {
    const float* sp_z    = (const float*)d_in[0];  // [B, V]
    const float* sp_w    = (const float*)d_in[1];  // [V, DIM]
    const float* encoded = (const float*)d_in[2];  // [B, DIM]

    const int B = in_sizes[2] / DIM;
    const int V = in_sizes[0] / B;

    float* out = (float*)d_out;
    float* attn_out = nullptr;
    float* idx_out  = nullptr;
    if (out_size >= B * (DIM + KTOP))     attn_out = out + (size_t)B * DIM;
    if (out_size >= B * (DIM + 2 * KTOP)) idx_out  = out + (size_t)B * (DIM + KTOP);

    fused_topk_attn_kernel<<<B, NTHREADS>>>(sp_z, sp_w, encoded,
                                            out, attn_out, idx_out, V);
}

// round 11
// speedup vs baseline: 1.4972x; 1.2066x over previous
#include <cuda_runtime.h>
#include <cstdint>

#define DIM      512
#define KTOP     5
#define NTHREADS 512
#define NWARPS   (NTHREADS / 32)
#define GROUP    4                    // float4s per thread per iteration (16 elems)
#define PER_ITER (NTHREADS * GROUP)   // float4s per block iteration
#define GMAX_IT  8                    // smem-deferred iterations (covers V<=131072)
#define GRP_MAX  1024
#define CAND_MAX 2048

#define NEG_INF (-__int_as_float(0x7F800000))

// Tie-break identical to jax.lax.top_k: higher value first, then lower index.
__device__ __forceinline__ bool better(float av, int ai, float bv, int bi) {
    return (av > bv) || (av == bv && ai < bi);
}

// Insert (nv, ni) into a descending-sorted top-5 list (cold path only).
__device__ __forceinline__ void insert5(float (&v)[KTOP], int (&ix)[KTOP],
                                        float nv, int ni) {
    if (!better(nv, ni, v[KTOP - 1], ix[KTOP - 1])) return;
    v[KTOP - 1] = nv;
    ix[KTOP - 1] = ni;
#pragma unroll
    for (int j = KTOP - 1; j > 0; --j) {
        if (better(v[j], ix[j], v[j - 1], ix[j - 1])) {
            float tv = v[j]; v[j] = v[j - 1]; v[j - 1] = tv;
            int   ti = ix[j]; ix[j] = ix[j - 1]; ix[j - 1] = ti;
        } else {
            break;
        }
    }
}

__device__ __forceinline__ void warp_merge_step(float (&v)[KTOP], int (&ix)[KTOP],
                                                int off) {
    float ov[KTOP];
    int   oi[KTOP];
#pragma unroll
    for (int j = 0; j < KTOP; ++j) {
        ov[j] = __shfl_xor_sync(0xFFFFFFFFu, v[j], off);
        oi[j] = __shfl_xor_sync(0xFFFFFFFFu, ix[j], off);
    }
#pragma unroll
    for (int j = 0; j < KTOP; ++j) insert5(v, ix, ov[j], oi[j]);
}

__device__ __forceinline__ float max4(float4 z) {
    return fmaxf(fmaxf(z.x, z.y), fmaxf(z.z, z.w));
}

// Cap regs at 32/thread so 4 CTAs (64 warps) fit per SM.
__global__ __launch_bounds__(NTHREADS, 4)
void fused_topk_attn_kernel(const float* __restrict__ sp_z,
                            const float* __restrict__ sp_w,
                            const float* __restrict__ encoded,
                            float* __restrict__ out,       // [B, DIM]
                            float* __restrict__ attn_out,  // [B, KTOP] or nullptr
                            float* __restrict__ idx_out,   // [B, KTOP] or nullptr
                            int V) {
    const int row  = blockIdx.x;
    const int tid  = threadIdx.x;
    const int lane = tid & 31;
    const int warp = tid >> 5;

    __shared__ float s_gmax[GMAX_IT][NTHREADS];   // 16 KB: deferred group maxes
    __shared__ float s_warpmax[NWARPS];
    __shared__ float s_t;
    __shared__ int   s_gcnt;
    __shared__ int   s_cnt;
    __shared__ int   s_gbase[GRP_MAX];
    __shared__ float s_cand_v[CAND_MAX];
    __shared__ int   s_cand_i[CAND_MAX];
    __shared__ int   s_idx[KTOP];
    __shared__ float s_red[NWARPS][KTOP];
    __shared__ float s_scores[KTOP];

    if (tid == 0) { s_gcnt = 0; s_cnt = 0; }
    __syncthreads();

    const size_t rowbase = (size_t)row * (size_t)V;
    const float4* zrow   = reinterpret_cast<const float4*>(sp_z + rowbase);
    const int nv4 = V >> 2;            // V % 4 == 0 for this problem (50000)

    const int nfull  = nv4 / PER_ITER;
    const int nfullc = min(nfull, GMAX_IT);   // deferred via smem (6 at V=50000)

    // ---- Pass 1: stream the WHOLE row once; no threshold on the critical path.
    // Record each 16-elem group max in smem; track the per-thread row max.
    float tm = NEG_INF;
    for (int it = 0; it < nfullc; ++it) {
        const int base = it * PER_ITER + tid;
        float4 z0 = __ldcs(zrow + base);
        float4 z1 = __ldcs(zrow + base +     NTHREADS);
        float4 z2 = __ldcs(zrow + base + 2 * NTHREADS);
        float4 z3 = __ldcs(zrow + base + 3 * NTHREADS);
        const float m = fmaxf(fmaxf(max4(z0), max4(z1)),
                              fmaxf(max4(z2), max4(z3)));
        s_gmax[it][tid] = m;           // conflict-free: consecutive tids
        tm = fmaxf(tm, m);
    }
    // Tail float4 (if any): keep its max in a register for post-threshold check.
    float tailm = NEG_INF;
    const int tail_i = nfull * PER_ITER + tid;
    if (tail_i < nv4) {
        tailm = max4(__ldcs(zrow + tail_i));
        tm = fmaxf(tm, tailm);
    }

    // ---- Threshold: 5th-largest warp-max over the FULL row.
    // The 5 largest warp-maxes are 5 distinct elements, so t <= global 5th:
    // (m >= t) provably keeps every top-5 element and leaves >= 5 survivors.
#pragma unroll
    for (int off = 16; off; off >>= 1)
        tm = fmaxf(tm, __shfl_xor_sync(0xFFFFFFFFu, tm, off));
    if (lane == 0) s_warpmax[warp] = tm;
    __syncthreads();

    if (warp == 0) {
        float wv = (lane < NWARPS) ? s_warpmax[lane] : NEG_INF;
        float tcur = NEG_INF;
#pragma unroll
        for (int r = 0; r < KTOP; ++r) {
            float m = wv;
#pragma unroll
            for (int off = 16; off; off >>= 1)
                m = fmaxf(m, __shfl_xor_sync(0xFFFFFFFFu, m, off));
            unsigned msk = __ballot_sync(0xFFFFFFFFu, wv == m);
            if (lane == __ffs(msk) - 1) wv = NEG_INF;   // remove one holder
            tcur = m;
        }
        if (lane == 0) s_t = tcur;
    }
    __syncthreads();
    const float t = s_t;

    // ---- Discover hit groups from smem-resident group maxes (no re-reads).
    for (int it = 0; it < nfullc; ++it) {
        if (s_gmax[it][tid] >= t) {
            int p = atomicAdd(&s_gcnt, 1);
            if (p < GRP_MAX) s_gbase[p] = it * PER_ITER + tid;
        }
    }
    // Iterations beyond the smem window (none at V=50000): inline filter.
    for (int it = GMAX_IT; it < nfull; ++it) {
        const int base = it * PER_ITER + tid;
        float4 z0 = __ldcs(zrow + base);
        float4 z1 = __ldcs(zrow + base +     NTHREADS);
        float4 z2 = __ldcs(zrow + base + 2 * NTHREADS);
        float4 z3 = __ldcs(zrow + base + 3 * NTHREADS);
        const float m = fmaxf(fmaxf(max4(z0), max4(z1)),
                              fmaxf(max4(z2), max4(z3)));
        if (m >= t) {
            int p = atomicAdd(&s_gcnt, 1);
            if (p < GRP_MAX) s_gbase[p] = base;
        }
    }
    // Tail: re-read the (L2-resident) float4 and push surviving elements.
    if (tailm >= t) {
        float4 z = __ldg(zrow + tail_i);
        const float zz[4] = {z.x, z.y, z.z, z.w};
#pragma unroll
        for (int r = 0; r < 4; ++r) {
            if (zz[r] >= t) {
                int p = atomicAdd(&s_cnt, 1);
                if (p < CAND_MAX) { s_cand_v[p] = zz[r]; s_cand_i[p] = (tail_i << 2) + r; }
            }
        }
    }

    // Prefetch the context-encoding element: latency overlaps expansion+merge.
    const float enc = __ldg(encoded + (size_t)row * DIM + tid);

    __syncthreads();

    // ---- Expand hit groups (16 elems on lanes 0..15): ballot-compact ----
    {
        const int ng = min(s_gcnt, GRP_MAX);
        for (int g = warp; g < ng; g += NWARPS) {
            const int base = s_gbase[g];
            float z = NEG_INF;
            int eidx = 0;
            if (lane < 16) {
                const int q = lane >> 2, r = lane & 3;
                const int fi = base + q * NTHREADS;      // float4 index
                eidx = (fi << 2) + r;
                z = __ldg(sp_z + rowbase + eidx);
            }
            const unsigned msk = __ballot_sync(0xFFFFFFFFu, z >= t);
            const int cnt = __popc(msk);
            int posbase = 0;
            if (lane == 0 && cnt) posbase = atomicAdd(&s_cnt, cnt);
            posbase = __shfl_sync(0xFFFFFFFFu, posbase, 0);
            const int off = __popc(msk & ((1u << lane) - 1));
            if ((z >= t) && (posbase + off) < CAND_MAX) {
                s_cand_v[posbase + off] = z;
                s_cand_i[posbase + off] = eidx;
            }
        }
    }
    __syncthreads();

    // ---- Exact top-5 (with lax.top_k tie-break) over ~30 candidates ----
    if (warp == 0) {
        float v[KTOP];
        int   ix[KTOP];
#pragma unroll
        for (int k = 0; k < KTOP; ++k) { v[k] = NEG_INF; ix[k] = 0x7FFFFFFF; }
        const int n = min(s_cnt, CAND_MAX);
        for (int c = lane; c < n; c += 32)
            insert5(v, ix, s_cand_v[c], s_cand_i[c]);
#pragma unroll
        for (int off = 16; off; off >>= 1) warp_merge_step(v, ix, off);
        if (lane == 0) {
#pragma unroll
            for (int k = 0; k < KTOP; ++k) s_idx[k] = ix[k];
        }
    }
    __syncthreads();

    // ---------------- Phase 2: gather + attention ----------------
    const int d = tid;   // DIM == NTHREADS == 512

    float w[KTOP];
    float partial[KTOP];
#pragma unroll
    for (int k = 0; k < KTOP; ++k) {
        w[k] = __ldg(sp_w + (size_t)s_idx[k] * DIM + d);
        partial[k] = w[k] * enc;
    }
#pragma unroll
    for (int off = 16; off; off >>= 1) {
#pragma unroll
        for (int k = 0; k < KTOP; ++k)
            partial[k] += __shfl_down_sync(0xFFFFFFFFu, partial[k], off);
    }
    if (lane == 0) {
#pragma unroll
        for (int k = 0; k < KTOP; ++k) s_red[warp][k] = partial[k];
    }
    __syncthreads();
    if (tid < KTOP) {
        float s = 0.f;
#pragma unroll
        for (int wq = 0; wq < NWARPS; ++wq) s += s_red[wq][tid];
        s_scores[tid] = s;
    }
    __syncthreads();

    float sc[KTOP];
#pragma unroll
    for (int k = 0; k < KTOP; ++k) sc[k] = s_scores[k];
    float mx = sc[0];
#pragma unroll
    for (int k = 1; k < KTOP; ++k) mx = fmaxf(mx, sc[k]);
    float e[KTOP];
    float esum = 0.f;
#pragma unroll
    for (int k = 0; k < KTOP; ++k) { e[k] = expf(sc[k] - mx); esum += e[k]; }
    const float inv = 1.0f / esum;

    float acc = 0.f;
#pragma unroll
    for (int k = 0; k < KTOP; ++k) acc += w[k] * (e[k] * inv);
    out[(size_t)row * DIM + d] = acc;

    if (tid < KTOP) {
        if (attn_out) attn_out[(size_t)row * KTOP + tid] = e[tid] * inv;
        if (idx_out)  idx_out[(size_t)row * KTOP + tid] = (float)s_idx[tid];
    }
}

extern "C" void kernel_launch(void* const* d_in, const int* in_sizes, int n_in,
                              void* d_out, int out_size) {
    const float* sp_z    = (const float*)d_in[0];  // [B, V]
    const float* sp_w    = (const float*)d_in[1];  // [V, DIM]
    const float* encoded = (const float*)d_in[2];  // [B, DIM]

    const int B = in_sizes[2] / DIM;
    const int V = in_sizes[0] / B;

    float* out = (float*)d_out;
    float* attn_out = nullptr;
    float* idx_out  = nullptr;
    if (out_size >= B * (DIM + KTOP))     attn_out = out + (size_t)B * DIM;
    if (out_size >= B * (DIM + 2 * KTOP)) idx_out  = out + (size_t)B * (DIM + KTOP);

    fused_topk_attn_kernel<<<B, NTHREADS>>>(sp_z, sp_w, encoded,
                                            out, attn_out, idx_out, V);
}